// round 16
// baseline (speedup 1.0000x reference)
#include <cuda_runtime.h>

#define TB 256
#define BATCH 1024
#define THIST 50
#define EIN 96
#define EH 128
#define G4 512
#define CDEH 64
#define CH 33
#define NMLP 128
#define NF 2112
#define NFPAD 2304
#define NZOUT 10000
#define NSTEPS 16
#define RPB 8
#define NBLK (BATCH/RPB)

__device__ float g_WT_ih0[EIN*G4];
__device__ float g_WT_hh0[EH*G4];
__device__ float g_WT_ih1[EH*G4];
__device__ float g_WT_hh1[EH*G4];
__device__ float g_WT_map[EH*CDEH];
__device__ float g_WT2[NMLP*NFPAD];
__device__ float g_WT_pred[CDEH*NZOUT];
__device__ float g_zbuf[BATCH*CDEH];

union F2U { float2 f; unsigned long long u; };
__device__ __forceinline__ float2 ffma2(float2 a, float2 b, float2 c) {
    F2U A,B,C,D; A.f=a; B.f=b; C.f=c;
    asm("fma.rn.f32x2 %0, %1, %2, %3;" : "=l"(D.u) : "l"(A.u), "l"(B.u), "l"(C.u));
    return D.f;
}
__device__ __forceinline__ float fsig(float x){ return 1.f/(1.f+__expf(-x)); }
__device__ __forceinline__ float ftanh_(float x){ return 1.f - 2.f/(__expf(2.f*x)+1.f); }

__global__ void prep_kernel(const float* __restrict__ Wih0, const float* __restrict__ Whh0,
                            const float* __restrict__ Wih1, const float* __restrict__ Whh1,
                            const float* __restrict__ Wmap, const float* __restrict__ W2,
                            const float* __restrict__ Wpred)
{
    int tid = blockIdx.x*blockDim.x + threadIdx.x;
    int nt = gridDim.x*blockDim.x;
    for (int i = tid; i < EIN*G4; i += nt){ int k=i/G4, g=i-k*G4; g_WT_ih0[i]=Wih0[g*EIN+k]; }
    for (int i = tid; i < EH*G4;  i += nt){ int k=i/G4, g=i-k*G4; g_WT_hh0[i]=Whh0[g*EH+k]; }
    for (int i = tid; i < EH*G4;  i += nt){ int k=i/G4, g=i-k*G4; g_WT_ih1[i]=Wih1[g*EH+k]; }
    for (int i = tid; i < EH*G4;  i += nt){ int k=i/G4, g=i-k*G4; g_WT_hh1[i]=Whh1[g*EH+k]; }
    for (int i = tid; i < EH*CDEH; i += nt){ int k=i/CDEH, j=i-k*CDEH; g_WT_map[i]=Wmap[j*EH+k]; }
    for (int i = tid; i < NMLP*NFPAD; i += nt){ int k=i/NFPAD, n=i-k*NFPAD; g_WT2[i]=(n<NF)?W2[n*NMLP+k]:0.f; }
    for (int i = tid; i < CDEH*NZOUT; i += nt){ int k=i/NZOUT, n=i-k*NZOUT; g_WT_pred[i]=Wpred[n*CDEH+k]; }
}

__global__ __launch_bounds__(TB) void lstm_kernel(
    const float* __restrict__ hist,
    const float* __restrict__ b_ih0, const float* __restrict__ b_hh0,
    const float* __restrict__ b_ih1, const float* __restrict__ b_hh1,
    const float* __restrict__ b_map)
{
    __shared__ __align__(16) float x_s[EIN][RPB];
    __shared__ __align__(16) float h0_s[EH][RPB];
    __shared__ __align__(16) float c0_s[EH][RPB];
    __shared__ __align__(16) float h1_s[EH][RPB];
    __shared__ __align__(16) float c1_s[EH][RPB];
    __shared__ __align__(16) float g_s[G4][RPB];

    const int tid = threadIdx.x;
    const int row0 = blockIdx.x * RPB;

    for (int i = tid; i < EH*RPB; i += TB){
        (&h0_s[0][0])[i]=0.f; (&c0_s[0][0])[i]=0.f;
        (&h1_s[0][0])[i]=0.f; (&c1_s[0][0])[i]=0.f;
    }
    const float bs0a = b_ih0[tid]     + b_hh0[tid];
    const float bs0b = b_ih0[tid+256] + b_hh0[tid+256];
    const float bs1a = b_ih1[tid]     + b_hh1[tid];
    const float bs1b = b_ih1[tid+256] + b_hh1[tid+256];
    __syncthreads();

    for (int t = 0; t < THIST; t++) {
        for (int i = tid; i < RPB*EIN; i += TB){
            int r = i/EIN, k = i - r*EIN;
            x_s[k][r] = hist[(row0+r)*(THIST*EIN) + t*EIN + k];
        }
        __syncthreads();
        { // layer 0 gates
            float2 aa[4], ab[4];
            #pragma unroll
            for (int p=0;p<4;p++){ aa[p]=make_float2(0,0); ab[p]=make_float2(0,0); }
            for (int k = 0; k < EIN; k++){
                float wa = g_WT_ih0[k*G4+tid], wb = g_WT_ih0[k*G4+tid+256];
                float2 wa2=make_float2(wa,wa), wb2=make_float2(wb,wb);
                const float2* xv = (const float2*)&x_s[k][0];
                #pragma unroll
                for (int p=0;p<4;p++){ float2 v=xv[p]; aa[p]=ffma2(v,wa2,aa[p]); ab[p]=ffma2(v,wb2,ab[p]); }
            }
            for (int k = 0; k < EH; k++){
                float wa = g_WT_hh0[k*G4+tid], wb = g_WT_hh0[k*G4+tid+256];
                float2 wa2=make_float2(wa,wa), wb2=make_float2(wb,wb);
                const float2* hv = (const float2*)&h0_s[k][0];
                #pragma unroll
                for (int p=0;p<4;p++){ float2 v=hv[p]; aa[p]=ffma2(v,wa2,aa[p]); ab[p]=ffma2(v,wb2,ab[p]); }
            }
            #pragma unroll
            for (int p=0;p<4;p++){
                float2 v=aa[p]; v.x+=bs0a; v.y+=bs0a; *(float2*)&g_s[tid][2*p]=v;
                float2 w=ab[p]; w.x+=bs0b; w.y+=bs0b; *(float2*)&g_s[tid+256][2*p]=w;
            }
        }
        __syncthreads();
        for (int q = tid; q < EH*RPB; q += TB){
            int u = q>>3, r = q&7;
            float gi=fsig(g_s[u][r]), gf=fsig(g_s[u+128][r]);
            float gg=ftanh_(g_s[u+256][r]), go=fsig(g_s[u+384][r]);
            float c = gf*c0_s[u][r] + gi*gg;
            c0_s[u][r]=c; h0_s[u][r]=go*ftanh_(c);
        }
        __syncthreads();
        { // layer 1 gates
            float2 aa[4], ab[4];
            #pragma unroll
            for (int p=0;p<4;p++){ aa[p]=make_float2(0,0); ab[p]=make_float2(0,0); }
            for (int k = 0; k < EH; k++){
                float wa = g_WT_ih1[k*G4+tid], wb = g_WT_ih1[k*G4+tid+256];
                float2 wa2=make_float2(wa,wa), wb2=make_float2(wb,wb);
                const float2* xv = (const float2*)&h0_s[k][0];
                #pragma unroll
                for (int p=0;p<4;p++){ float2 v=xv[p]; aa[p]=ffma2(v,wa2,aa[p]); ab[p]=ffma2(v,wb2,ab[p]); }
            }
            for (int k = 0; k < EH; k++){
                float wa = g_WT_hh1[k*G4+tid], wb = g_WT_hh1[k*G4+tid+256];
                float2 wa2=make_float2(wa,wa), wb2=make_float2(wb,wb);
                const float2* hv = (const float2*)&h1_s[k][0];
                #pragma unroll
                for (int p=0;p<4;p++){ float2 v=hv[p]; aa[p]=ffma2(v,wa2,aa[p]); ab[p]=ffma2(v,wb2,ab[p]); }
            }
            #pragma unroll
            for (int p=0;p<4;p++){
                float2 v=aa[p]; v.x+=bs1a; v.y+=bs1a; *(float2*)&g_s[tid][2*p]=v;
                float2 w=ab[p]; w.x+=bs1b; w.y+=bs1b; *(float2*)&g_s[tid+256][2*p]=w;
            }
        }
        __syncthreads();
        for (int q = tid; q < EH*RPB; q += TB){
            int u = q>>3, r = q&7;
            float gi=fsig(g_s[u][r]), gf=fsig(g_s[u+128][r]);
            float gg=ftanh_(g_s[u+256][r]), go=fsig(g_s[u+384][r]);
            float c = gf*c1_s[u][r] + gi*gg;
            c1_s[u][r]=c; h1_s[u][r]=go*ftanh_(c);
        }
        __syncthreads();
    }
    for (int q = tid; q < RPB*CDEH; q += TB){
        int r = q>>6, j = q&63;
        float acc = b_map[j];
        for (int k = 0; k < EH; k++) acc = fmaf(h1_s[k][r], g_WT_map[k*CDEH+j], acc);
        g_zbuf[(row0+r)*CDEH + j] = ftanh_(acc);
    }
}

__global__ __launch_bounds__(TB) void cde_kernel(
    const float* __restrict__ coeffs, const float* __restrict__ times,
    const float* __restrict__ gamma_, const float* __restrict__ beta_,
    const float* __restrict__ W1, const float* __restrict__ b1,
    const float* __restrict__ b2)
{
    extern __shared__ float sm[];
    float* W1T_s = sm;                 // 8192
    float* b1_s  = W1T_s + 8192;       // 128
    float* b2_s  = b1_s + 128;         // 2112
    float* gam_s = b2_s + NF;          // 64
    float* bet_s = gam_s + 64;         // 64
    float* cf_s  = bet_s + 64;         // 4224
    float* z_s   = cf_s + 4224;        // 512
    float* zt_s  = z_s + 512;          // 512
    float* zn_s  = zt_s + 512;         // 512
    float* a_s   = zn_s + 512;         // 1024
    float* dX_s  = a_s + 1024;         // 264
    float* k_s   = dX_s + 264;         // 3072
    float* f_s   = k_s + 3072;         // 16896

    const int tid = threadIdx.x;
    const int row0 = blockIdx.x * RPB;

    for (int i = tid; i < CDEH*NMLP; i += TB){ int k=i>>7, j=i&127; W1T_s[k*128+j] = W1[j*CDEH+k]; }
    for (int i = tid; i < NMLP; i += TB) b1_s[i] = b1[i];
    for (int i = tid; i < NF;   i += TB) b2_s[i] = b2[i];
    if (tid < CDEH){ gam_s[tid]=gamma_[tid]; bet_s[tid]=beta_[tid]; }
    for (int i = tid; i < RPB*528; i += TB){ int r=i/528, q=i-r*528; cf_s[r*528+q] = coeffs[(row0+r)*528 + q]; }
    for (int i = tid; i < 512; i += TB){ int r=i&7, h=i>>3; z_s[h*8+r] = g_zbuf[(row0+r)*CDEH + h]; }
    const float t0 = times[0], t1 = times[1];
    const float dt = (t1-t0)/16.f, seg = (t1-t0)/4.f;
    __syncthreads();

    auto vf = [&](float tt, const float* zin, float* kout){
        {
            float rel = (tt - t0)/seg;
            int idx = (int)floorf(rel);
            idx = max(0, min(3, idx));
            float u = tt - (t0 + (float)idx*seg);
            for (int q = tid; q < CH*RPB; q += TB){
                int r = q&7, i = q>>3;
                const float* cc = &cf_s[r*528 + idx*132];
                dX_s[i*8+r] = cc[33+i] + 2.f*cc[66+i]*u + 3.f*cc[99+i]*(u*u);
            }
        }
        {
            int w = tid>>5, lane = tid&31;
            float v0 = zin[lane*8+w], v1 = zin[(lane+32)*8+w];
            float s = v0+v1;
            #pragma unroll
            for (int o=16;o>0;o>>=1) s += __shfl_xor_sync(0xffffffffu, s, o);
            float mu = s*(1.f/64.f);
            float d0=v0-mu, d1=v1-mu;
            float q2 = d0*d0 + d1*d1;
            #pragma unroll
            for (int o=16;o>0;o>>=1) q2 += __shfl_xor_sync(0xffffffffu, q2, o);
            float rstd = rsqrtf(q2*(1.f/64.f) + 1e-5f);
            zn_s[lane*8+w]      = d0*rstd*gam_s[lane]    + bet_s[lane];
            zn_s[(lane+32)*8+w] = d1*rstd*gam_s[lane+32] + bet_s[lane+32];
        }
        __syncthreads();
        {
            int j = tid&127, pa = tid>>7;
            float2 acc0=make_float2(0,0), acc1=make_float2(0,0);
            for (int k = 0; k < CDEH; k++){
                float w = W1T_s[k*128+j];
                float2 w2 = make_float2(w,w);
                float2 za = *(const float2*)&zn_s[k*8 + 2*pa];
                float2 zb = *(const float2*)&zn_s[k*8 + 2*(pa+2)];
                acc0 = ffma2(za, w2, acc0);
                acc1 = ffma2(zb, w2, acc1);
            }
            float bb = b1_s[j];
            a_s[j*8 + 2*pa]         = fmaxf(acc0.x+bb, 0.f);
            a_s[j*8 + 2*pa+1]       = fmaxf(acc0.y+bb, 0.f);
            a_s[j*8 + 2*(pa+2)]     = fmaxf(acc1.x+bb, 0.f);
            a_s[j*8 + 2*(pa+2)+1]   = fmaxf(acc1.y+bb, 0.f);
        }
        __syncthreads();
        {
            float2 acc[9][4];
            #pragma unroll
            for (int j=0;j<9;j++)
                #pragma unroll
                for (int p=0;p<4;p++) acc[j][p]=make_float2(0,0);
            const float* wbase = g_WT2 + tid;
            #pragma unroll 2
            for (int k = 0; k < NMLP; k++){
                float2 av[4];
                #pragma unroll
                for (int p=0;p<4;p++) av[p] = *(const float2*)&a_s[k*8 + 2*p];
                const float* wr = wbase + k*NFPAD;
                #pragma unroll
                for (int j=0;j<9;j++){
                    float wv = wr[j*256];
                    float2 w2 = make_float2(wv,wv);
                    #pragma unroll
                    for (int p=0;p<4;p++) acc[j][p] = ffma2(av[p], w2, acc[j][p]);
                }
            }
            #pragma unroll
            for (int j=0;j<9;j++){
                int n = tid + j*256;
                if (n < NF){
                    float bb = b2_s[n];
                    #pragma unroll
                    for (int p=0;p<4;p++){
                        f_s[n*8 + 2*p]   = ftanh_(acc[j][p].x + bb);
                        f_s[n*8 + 2*p+1] = ftanh_(acc[j][p].y + bb);
                    }
                }
            }
        }
        __syncthreads();
        for (int q = tid; q < 512; q += TB){
            int r = q&7, h = q>>3;
            float s = 0.f;
            const float* fp = &f_s[h*CH*8 + r];
            #pragma unroll
            for (int i=0;i<CH;i++) s = fmaf(fp[i*8], dX_s[i*8+r], s);
            kout[h*8+r] = s;
        }
        __syncthreads();
    };

    const float A21=(float)(1.0/5.0);
    const float A31=(float)(3.0/40.0), A32=(float)(9.0/40.0);
    const float A41=(float)(44.0/45.0), A42=(float)(-56.0/15.0), A43=(float)(32.0/9.0);
    const float A51=(float)(19372.0/6561.0), A52=(float)(-25360.0/2187.0), A53=(float)(64448.0/6561.0), A54=(float)(-212.0/729.0);
    const float A61=(float)(9017.0/3168.0), A62=(float)(-355.0/33.0), A63=(float)(46732.0/5247.0), A64=(float)(49.0/176.0), A65=(float)(-5103.0/18656.0);
    const float B1=(float)(35.0/384.0), B3=(float)(500.0/1113.0), B4=(float)(125.0/192.0), B5=(float)(-2187.0/6784.0), B6=(float)(11.0/84.0);

    float* K1=k_s; float* K2=k_s+512; float* K3=k_s+1024;
    float* K4=k_s+1536; float* K5=k_s+2048; float* K6=k_s+2560;

    for (int st = 0; st < NSTEPS; st++){
        float tb = t0 + (float)st*dt;
        vf(tb, z_s, K1);
        for (int q=tid;q<512;q+=TB) zt_s[q] = z_s[q] + dt*(A21*K1[q]);
        __syncthreads();
        vf(tb + dt/5.f, zt_s, K2);
        for (int q=tid;q<512;q+=TB) zt_s[q] = z_s[q] + dt*(A31*K1[q] + A32*K2[q]);
        __syncthreads();
        vf(tb + 3.f*dt/10.f, zt_s, K3);
        for (int q=tid;q<512;q+=TB) zt_s[q] = z_s[q] + dt*(A41*K1[q] + A42*K2[q] + A43*K3[q]);
        __syncthreads();
        vf(tb + 4.f*dt/5.f, zt_s, K4);
        for (int q=tid;q<512;q+=TB) zt_s[q] = z_s[q] + dt*(A51*K1[q] + A52*K2[q] + A53*K3[q] + A54*K4[q]);
        __syncthreads();
        vf(tb + 8.f*dt/9.f, zt_s, K5);
        for (int q=tid;q<512;q+=TB) zt_s[q] = z_s[q] + dt*(A61*K1[q] + A62*K2[q] + A63*K3[q] + A64*K4[q] + A65*K5[q]);
        __syncthreads();
        vf(tb + dt, zt_s, K6);
        for (int q=tid;q<512;q+=TB) z_s[q] = z_s[q] + dt*(B1*K1[q] + B3*K3[q] + B4*K4[q] + B5*K5[q] + B6*K6[q]);
        __syncthreads();
    }
    for (int i = tid; i < 512; i += TB){ int r=i&7, h=i>>3; g_zbuf[(row0+r)*CDEH + h] = z_s[h*8+r]; }
}

__global__ __launch_bounds__(TB) void pred_kernel(const float* __restrict__ b_pred, float* __restrict__ out)
{
    __shared__ float z_s[CDEH*16];
    const int tid = threadIdx.x;
    const int row0 = blockIdx.y * 16;
    for (int i = tid; i < 16*CDEH; i += TB){ int r=i>>6, k=i&63; z_s[k*16+r] = g_zbuf[(row0+r)*CDEH + k]; }
    __syncthreads();
    int n = blockIdx.x*TB + tid;
    if (n >= NZOUT) return;
    float acc[16];
    #pragma unroll
    for (int r=0;r<16;r++) acc[r]=0.f;
    for (int k = 0; k < CDEH; k++){
        float w = g_WT_pred[k*NZOUT + n];
        #pragma unroll
        for (int r=0;r<16;r++) acc[r] = fmaf(z_s[k*16+r], w, acc[r]);
    }
    float bb = b_pred[n];
    #pragma unroll
    for (int r=0;r<16;r++) out[(row0+r)*NZOUT + n] = acc[r] + bb;
}

extern "C" void kernel_launch(void* const* d_in, const int* in_sizes, int n_in,
                              void* d_out, int out_size)
{
    const float* hist   = (const float*)d_in[0];
    const float* coeffs = (const float*)d_in[1];
    const float* times  = (const float*)d_in[2];
    const float* Wih0   = (const float*)d_in[3];
    const float* Whh0   = (const float*)d_in[4];
    const float* bih0   = (const float*)d_in[5];
    const float* bhh0   = (const float*)d_in[6];
    const float* Wih1   = (const float*)d_in[7];
    const float* Whh1   = (const float*)d_in[8];
    const float* bih1   = (const float*)d_in[9];
    const float* bhh1   = (const float*)d_in[10];
    const float* Wmap   = (const float*)d_in[11];
    const float* bmap   = (const float*)d_in[12];
    const float* gamma_ = (const float*)d_in[13];
    const float* beta_  = (const float*)d_in[14];
    const float* W1     = (const float*)d_in[15];
    const float* b1     = (const float*)d_in[16];
    const float* W2     = (const float*)d_in[17];
    const float* b2     = (const float*)d_in[18];
    const float* Wpred  = (const float*)d_in[19];
    const float* bpred  = (const float*)d_in[20];
    float* out = (float*)d_out;

    prep_kernel<<<256, 256>>>(Wih0, Whh0, Wih1, Whh1, Wmap, W2, Wpred);
    lstm_kernel<<<NBLK, TB>>>(hist, bih0, bhh0, bih1, bhh1, bmap);

    int smem_bytes = 37576 * 4;
    cudaFuncSetAttribute(cde_kernel, cudaFuncAttributeMaxDynamicSharedMemorySize, smem_bytes);
    cde_kernel<<<NBLK, TB, smem_bytes>>>(coeffs, times, gamma_, beta_, W1, b1, b2);

    dim3 pg((NZOUT + TB - 1) / TB, BATCH / 16);
    pred_kernel<<<pg, TB>>>(bpred, out);
}

// round 17
// speedup vs baseline: 1.0045x; 1.0045x over previous
#include <cuda_runtime.h>

#define TB 256
#define BATCH 1024
#define THIST 50
#define EIN 96
#define EH 128
#define G4 512
#define CDEH 64
#define CH 33
#define NMLP 128
#define NF 2112
#define NFPAD 2304
#define NZOUT 10000
#define NSTEPS 16
#define RPB 8
#define NBLK (BATCH/RPB)

__device__ float g_WT_ih0[EIN*G4];
__device__ float g_WT_hh0[EH*G4];
__device__ float g_WT_ih1[EH*G4];
__device__ float g_WT_hh1[EH*G4];
__device__ float g_WT_map[EH*CDEH];
__device__ float g_WT2[NMLP*NFPAD];
__device__ float g_WT_pred[CDEH*NZOUT];
__device__ float g_zbuf[BATCH*CDEH];

union F2U { float2 f; unsigned long long u; };
__device__ __forceinline__ float2 ffma2(float2 a, float2 b, float2 c) {
    F2U A,B,C,D; A.f=a; B.f=b; C.f=c;
    asm("fma.rn.f32x2 %0, %1, %2, %3;" : "=l"(D.u) : "l"(A.u), "l"(B.u), "l"(C.u));
    return D.f;
}
__device__ __forceinline__ float fsig(float x){ return 1.f/(1.f+__expf(-x)); }
__device__ __forceinline__ float ftanh_(float x){ return 1.f - 2.f/(__expf(2.f*x)+1.f); }

__global__ void prep_kernel(const float* __restrict__ Wih0, const float* __restrict__ Whh0,
                            const float* __restrict__ Wih1, const float* __restrict__ Whh1,
                            const float* __restrict__ Wmap, const float* __restrict__ W2,
                            const float* __restrict__ Wpred)
{
    int tid = blockIdx.x*blockDim.x + threadIdx.x;
    int nt = gridDim.x*blockDim.x;
    for (int i = tid; i < EIN*G4; i += nt){ int k=i/G4, g=i-k*G4; g_WT_ih0[i]=Wih0[g*EIN+k]; }
    for (int i = tid; i < EH*G4;  i += nt){ int k=i/G4, g=i-k*G4; g_WT_hh0[i]=Whh0[g*EH+k]; }
    for (int i = tid; i < EH*G4;  i += nt){ int k=i/G4, g=i-k*G4; g_WT_ih1[i]=Wih1[g*EH+k]; }
    for (int i = tid; i < EH*G4;  i += nt){ int k=i/G4, g=i-k*G4; g_WT_hh1[i]=Whh1[g*EH+k]; }
    for (int i = tid; i < EH*CDEH; i += nt){ int k=i/CDEH, j=i-k*CDEH; g_WT_map[i]=Wmap[j*EH+k]; }
    for (int i = tid; i < NMLP*NFPAD; i += nt){ int k=i/NFPAD, n=i-k*NFPAD; g_WT2[i]=(n<NF)?W2[n*NMLP+k]:0.f; }
    for (int i = tid; i < CDEH*NZOUT; i += nt){ int k=i/NZOUT, n=i-k*NZOUT; g_WT_pred[i]=Wpred[n*CDEH+k]; }
}

__global__ __launch_bounds__(TB) void lstm_kernel(
    const float* __restrict__ hist,
    const float* __restrict__ b_ih0, const float* __restrict__ b_hh0,
    const float* __restrict__ b_ih1, const float* __restrict__ b_hh1,
    const float* __restrict__ b_map)
{
    __shared__ __align__(16) float x_s[EIN][RPB];
    __shared__ __align__(16) float h0_s[EH][RPB];
    __shared__ __align__(16) float c0_s[EH][RPB];
    __shared__ __align__(16) float h1_s[EH][RPB];
    __shared__ __align__(16) float c1_s[EH][RPB];
    __shared__ __align__(16) float g_s[G4][RPB];

    const int tid = threadIdx.x;
    const int row0 = blockIdx.x * RPB;

    for (int i = tid; i < EH*RPB; i += TB){
        (&h0_s[0][0])[i]=0.f; (&c0_s[0][0])[i]=0.f;
        (&h1_s[0][0])[i]=0.f; (&c1_s[0][0])[i]=0.f;
    }
    const float bs0a = b_ih0[tid]     + b_hh0[tid];
    const float bs0b = b_ih0[tid+256] + b_hh0[tid+256];
    const float bs1a = b_ih1[tid]     + b_hh1[tid];
    const float bs1b = b_ih1[tid+256] + b_hh1[tid+256];
    __syncthreads();

    for (int t = 0; t < THIST; t++) {
        for (int i = tid; i < RPB*EIN; i += TB){
            int r = i/EIN, k = i - r*EIN;
            x_s[k][r] = hist[(row0+r)*(THIST*EIN) + t*EIN + k];
        }
        __syncthreads();
        { // layer 0 gates
            float2 aa[4], ab[4];
            #pragma unroll
            for (int p=0;p<4;p++){ aa[p]=make_float2(0,0); ab[p]=make_float2(0,0); }
            for (int k = 0; k < EIN; k++){
                float wa = g_WT_ih0[k*G4+tid], wb = g_WT_ih0[k*G4+tid+256];
                float2 wa2=make_float2(wa,wa), wb2=make_float2(wb,wb);
                const float2* xv = (const float2*)&x_s[k][0];
                #pragma unroll
                for (int p=0;p<4;p++){ float2 v=xv[p]; aa[p]=ffma2(v,wa2,aa[p]); ab[p]=ffma2(v,wb2,ab[p]); }
            }
            for (int k = 0; k < EH; k++){
                float wa = g_WT_hh0[k*G4+tid], wb = g_WT_hh0[k*G4+tid+256];
                float2 wa2=make_float2(wa,wa), wb2=make_float2(wb,wb);
                const float2* hv = (const float2*)&h0_s[k][0];
                #pragma unroll
                for (int p=0;p<4;p++){ float2 v=hv[p]; aa[p]=ffma2(v,wa2,aa[p]); ab[p]=ffma2(v,wb2,ab[p]); }
            }
            #pragma unroll
            for (int p=0;p<4;p++){
                float2 v=aa[p]; v.x+=bs0a; v.y+=bs0a; *(float2*)&g_s[tid][2*p]=v;
                float2 w=ab[p]; w.x+=bs0b; w.y+=bs0b; *(float2*)&g_s[tid+256][2*p]=w;
            }
        }
        __syncthreads();
        for (int q = tid; q < EH*RPB; q += TB){
            int u = q>>3, r = q&7;
            float gi=fsig(g_s[u][r]), gf=fsig(g_s[u+128][r]);
            float gg=ftanh_(g_s[u+256][r]), go=fsig(g_s[u+384][r]);
            float c = gf*c0_s[u][r] + gi*gg;
            c0_s[u][r]=c; h0_s[u][r]=go*ftanh_(c);
        }
        __syncthreads();
        { // layer 1 gates
            float2 aa[4], ab[4];
            #pragma unroll
            for (int p=0;p<4;p++){ aa[p]=make_float2(0,0); ab[p]=make_float2(0,0); }
            for (int k = 0; k < EH; k++){
                float wa = g_WT_ih1[k*G4+tid], wb = g_WT_ih1[k*G4+tid+256];
                float2 wa2=make_float2(wa,wa), wb2=make_float2(wb,wb);
                const float2* xv = (const float2*)&h0_s[k][0];
                #pragma unroll
                for (int p=0;p<4;p++){ float2 v=xv[p]; aa[p]=ffma2(v,wa2,aa[p]); ab[p]=ffma2(v,wb2,ab[p]); }
            }
            for (int k = 0; k < EH; k++){
                float wa = g_WT_hh1[k*G4+tid], wb = g_WT_hh1[k*G4+tid+256];
                float2 wa2=make_float2(wa,wa), wb2=make_float2(wb,wb);
                const float2* hv = (const float2*)&h1_s[k][0];
                #pragma unroll
                for (int p=0;p<4;p++){ float2 v=hv[p]; aa[p]=ffma2(v,wa2,aa[p]); ab[p]=ffma2(v,wb2,ab[p]); }
            }
            #pragma unroll
            for (int p=0;p<4;p++){
                float2 v=aa[p]; v.x+=bs1a; v.y+=bs1a; *(float2*)&g_s[tid][2*p]=v;
                float2 w=ab[p]; w.x+=bs1b; w.y+=bs1b; *(float2*)&g_s[tid+256][2*p]=w;
            }
        }
        __syncthreads();
        for (int q = tid; q < EH*RPB; q += TB){
            int u = q>>3, r = q&7;
            float gi=fsig(g_s[u][r]), gf=fsig(g_s[u+128][r]);
            float gg=ftanh_(g_s[u+256][r]), go=fsig(g_s[u+384][r]);
            float c = gf*c1_s[u][r] + gi*gg;
            c1_s[u][r]=c; h1_s[u][r]=go*ftanh_(c);
        }
        __syncthreads();
    }
    for (int q = tid; q < RPB*CDEH; q += TB){
        int r = q>>6, j = q&63;
        float acc = b_map[j];
        for (int k = 0; k < EH; k++) acc = fmaf(h1_s[k][r], g_WT_map[k*CDEH+j], acc);
        g_zbuf[(row0+r)*CDEH + j] = ftanh_(acc);
    }
}

__global__ __launch_bounds__(TB) void cde_kernel(
    const float* __restrict__ coeffs, const float* __restrict__ times,
    const float* __restrict__ gamma_, const float* __restrict__ beta_,
    const float* __restrict__ W1, const float* __restrict__ b1,
    const float* __restrict__ b2)
{
    extern __shared__ float sm[];
    float* W1T_s = sm;                 // 8192
    float* b1_s  = W1T_s + 8192;       // 128
    float* b2_s  = b1_s + 128;         // 2112
    float* gam_s = b2_s + NF;          // 64
    float* bet_s = gam_s + 64;         // 64
    float* cf_s  = bet_s + 64;         // 4224
    float* z_s   = cf_s + 4224;        // 512
    float* zt_s  = z_s + 512;          // 512
    float* zn_s  = zt_s + 512;         // 512
    float* a_s   = zn_s + 512;         // 1024
    float* dX_s  = a_s + 1024;         // 264
    float* k_s   = dX_s + 264;         // 3072
    float* f_s   = k_s + 3072;         // 16896

    const int tid = threadIdx.x;
    const int row0 = blockIdx.x * RPB;

    for (int i = tid; i < CDEH*NMLP; i += TB){ int k=i>>7, j=i&127; W1T_s[k*128+j] = W1[j*CDEH+k]; }
    for (int i = tid; i < NMLP; i += TB) b1_s[i] = b1[i];
    for (int i = tid; i < NF;   i += TB) b2_s[i] = b2[i];
    if (tid < CDEH){ gam_s[tid]=gamma_[tid]; bet_s[tid]=beta_[tid]; }
    for (int i = tid; i < RPB*528; i += TB){ int r=i/528, q=i-r*528; cf_s[r*528+q] = coeffs[(row0+r)*528 + q]; }
    for (int i = tid; i < 512; i += TB){ int r=i&7, h=i>>3; z_s[h*8+r] = g_zbuf[(row0+r)*CDEH + h]; }
    const float t0 = times[0], t1 = times[1];
    const float dt = (t1-t0)/16.f, seg = (t1-t0)/4.f;
    __syncthreads();

    auto vf = [&](float tt, const float* zin, float* kout){
        {
            float rel = (tt - t0)/seg;
            int idx = (int)floorf(rel);
            idx = max(0, min(3, idx));
            float u = tt - (t0 + (float)idx*seg);
            for (int q = tid; q < CH*RPB; q += TB){
                int r = q&7, i = q>>3;
                const float* cc = &cf_s[r*528 + idx*132];
                dX_s[i*8+r] = cc[33+i] + 2.f*cc[66+i]*u + 3.f*cc[99+i]*(u*u);
            }
        }
        {
            int w = tid>>5, lane = tid&31;
            float v0 = zin[lane*8+w], v1 = zin[(lane+32)*8+w];
            float s = v0+v1;
            #pragma unroll
            for (int o=16;o>0;o>>=1) s += __shfl_xor_sync(0xffffffffu, s, o);
            float mu = s*(1.f/64.f);
            float d0=v0-mu, d1=v1-mu;
            float q2 = d0*d0 + d1*d1;
            #pragma unroll
            for (int o=16;o>0;o>>=1) q2 += __shfl_xor_sync(0xffffffffu, q2, o);
            float rstd = rsqrtf(q2*(1.f/64.f) + 1e-5f);
            zn_s[lane*8+w]      = d0*rstd*gam_s[lane]    + bet_s[lane];
            zn_s[(lane+32)*8+w] = d1*rstd*gam_s[lane+32] + bet_s[lane+32];
        }
        __syncthreads();
        {
            int j = tid&127, pa = tid>>7;
            float2 acc0=make_float2(0,0), acc1=make_float2(0,0);
            for (int k = 0; k < CDEH; k++){
                float w = W1T_s[k*128+j];
                float2 w2 = make_float2(w,w);
                float2 za = *(const float2*)&zn_s[k*8 + 2*pa];
                float2 zb = *(const float2*)&zn_s[k*8 + 2*(pa+2)];
                acc0 = ffma2(za, w2, acc0);
                acc1 = ffma2(zb, w2, acc1);
            }
            float bb = b1_s[j];
            a_s[j*8 + 2*pa]         = fmaxf(acc0.x+bb, 0.f);
            a_s[j*8 + 2*pa+1]       = fmaxf(acc0.y+bb, 0.f);
            a_s[j*8 + 2*(pa+2)]     = fmaxf(acc1.x+bb, 0.f);
            a_s[j*8 + 2*(pa+2)+1]   = fmaxf(acc1.y+bb, 0.f);
        }
        __syncthreads();
        {
            float2 acc[9][4];
            #pragma unroll
            for (int j=0;j<9;j++)
                #pragma unroll
                for (int p=0;p<4;p++) acc[j][p]=make_float2(0,0);
            const float* wbase = g_WT2 + tid;
            #pragma unroll 2
            for (int k = 0; k < NMLP; k++){
                float2 av[4];
                #pragma unroll
                for (int p=0;p<4;p++) av[p] = *(const float2*)&a_s[k*8 + 2*p];
                const float* wr = wbase + k*NFPAD;
                #pragma unroll
                for (int j=0;j<9;j++){
                    float wv = wr[j*256];
                    float2 w2 = make_float2(wv,wv);
                    #pragma unroll
                    for (int p=0;p<4;p++) acc[j][p] = ffma2(av[p], w2, acc[j][p]);
                }
            }
            #pragma unroll
            for (int j=0;j<9;j++){
                int n = tid + j*256;
                if (n < NF){
                    float bb = b2_s[n];
                    #pragma unroll
                    for (int p=0;p<4;p++){
                        f_s[n*8 + 2*p]   = ftanh_(acc[j][p].x + bb);
                        f_s[n*8 + 2*p+1] = ftanh_(acc[j][p].y + bb);
                    }
                }
            }
        }
        __syncthreads();
        for (int q = tid; q < 512; q += TB){
            int r = q&7, h = q>>3;
            float s = 0.f;
            const float* fp = &f_s[h*CH*8 + r];
            #pragma unroll
            for (int i=0;i<CH;i++) s = fmaf(fp[i*8], dX_s[i*8+r], s);
            kout[h*8+r] = s;
        }
        __syncthreads();
    };

    const float A21=(float)(1.0/5.0);
    const float A31=(float)(3.0/40.0), A32=(float)(9.0/40.0);
    const float A41=(float)(44.0/45.0), A42=(float)(-56.0/15.0), A43=(float)(32.0/9.0);
    const float A51=(float)(19372.0/6561.0), A52=(float)(-25360.0/2187.0), A53=(float)(64448.0/6561.0), A54=(float)(-212.0/729.0);
    const float A61=(float)(9017.0/3168.0), A62=(float)(-355.0/33.0), A63=(float)(46732.0/5247.0), A64=(float)(49.0/176.0), A65=(float)(-5103.0/18656.0);
    const float B1=(float)(35.0/384.0), B3=(float)(500.0/1113.0), B4=(float)(125.0/192.0), B5=(float)(-2187.0/6784.0), B6=(float)(11.0/84.0);

    float* K1=k_s; float* K2=k_s+512; float* K3=k_s+1024;
    float* K4=k_s+1536; float* K5=k_s+2048; float* K6=k_s+2560;

    for (int st = 0; st < NSTEPS; st++){
        float tb = t0 + (float)st*dt;
        vf(tb, z_s, K1);
        for (int q=tid;q<512;q+=TB) zt_s[q] = z_s[q] + dt*(A21*K1[q]);
        __syncthreads();
        vf(tb + dt/5.f, zt_s, K2);
        for (int q=tid;q<512;q+=TB) zt_s[q] = z_s[q] + dt*(A31*K1[q] + A32*K2[q]);
        __syncthreads();
        vf(tb + 3.f*dt/10.f, zt_s, K3);
        for (int q=tid;q<512;q+=TB) zt_s[q] = z_s[q] + dt*(A41*K1[q] + A42*K2[q] + A43*K3[q]);
        __syncthreads();
        vf(tb + 4.f*dt/5.f, zt_s, K4);
        for (int q=tid;q<512;q+=TB) zt_s[q] = z_s[q] + dt*(A51*K1[q] + A52*K2[q] + A53*K3[q] + A54*K4[q]);
        __syncthreads();
        vf(tb + 8.f*dt/9.f, zt_s, K5);
        for (int q=tid;q<512;q+=TB) zt_s[q] = z_s[q] + dt*(A61*K1[q] + A62*K2[q] + A63*K3[q] + A64*K4[q] + A65*K5[q]);
        __syncthreads();
        vf(tb + dt, zt_s, K6);
        for (int q=tid;q<512;q+=TB) z_s[q] = z_s[q] + dt*(B1*K1[q] + B3*K3[q] + B4*K4[q] + B5*K5[q] + B6*K6[q]);
        __syncthreads();
    }
    for (int i = tid; i < 512; i += TB){ int r=i&7, h=i>>3; g_zbuf[(row0+r)*CDEH + h] = z_s[h*8+r]; }
}

__global__ __launch_bounds__(TB) void pred_kernel(const float* __restrict__ b_pred, float* __restrict__ out)
{
    __shared__ float z_s[CDEH*16];
    const int tid = threadIdx.x;
    const int row0 = blockIdx.y * 16;
    for (int i = tid; i < 16*CDEH; i += TB){ int r=i>>6, k=i&63; z_s[k*16+r] = g_zbuf[(row0+r)*CDEH + k]; }
    __syncthreads();
    int n = blockIdx.x*TB + tid;
    if (n >= NZOUT) return;
    float acc[16];
    #pragma unroll
    for (int r=0;r<16;r++) acc[r]=0.f;
    for (int k = 0; k < CDEH; k++){
        float w = g_WT_pred[k*NZOUT + n];
        #pragma unroll
        for (int r=0;r<16;r++) acc[r] = fmaf(z_s[k*16+r], w, acc[r]);
    }
    float bb = b_pred[n];
    #pragma unroll
    for (int r=0;r<16;r++) out[(row0+r)*NZOUT + n] = acc[r] + bb;
}

extern "C" void kernel_launch(void* const* d_in, const int* in_sizes, int n_in,
                              void* d_out, int out_size)
{
    const float* hist   = (const float*)d_in[0];
    const float* coeffs = (const float*)d_in[1];
    const float* times  = (const float*)d_in[2];
    const float* Wih0   = (const float*)d_in[3];
    const float* Whh0   = (const float*)d_in[4];
    const float* bih0   = (const float*)d_in[5];
    const float* bhh0   = (const float*)d_in[6];
    const float* Wih1   = (const float*)d_in[7];
    const float* Whh1   = (const float*)d_in[8];
    const float* bih1   = (const float*)d_in[9];
    const float* bhh1   = (const float*)d_in[10];
    const float* Wmap   = (const float*)d_in[11];
    const float* bmap   = (const float*)d_in[12];
    const float* gamma_ = (const float*)d_in[13];
    const float* beta_  = (const float*)d_in[14];
    const float* W1     = (const float*)d_in[15];
    const float* b1     = (const float*)d_in[16];
    const float* W2     = (const float*)d_in[17];
    const float* b2     = (const float*)d_in[18];
    const float* Wpred  = (const float*)d_in[19];
    const float* bpred  = (const float*)d_in[20];
    float* out = (float*)d_out;

    prep_kernel<<<256, 256>>>(Wih0, Whh0, Wih1, Whh1, Wmap, W2, Wpred);
    lstm_kernel<<<NBLK, TB>>>(hist, bih0, bhh0, bih1, bhh1, bmap);

    int smem_bytes = 37576 * 4;
    cudaFuncSetAttribute(cde_kernel, cudaFuncAttributeMaxDynamicSharedMemorySize, smem_bytes);
    cde_kernel<<<NBLK, TB, smem_bytes>>>(coeffs, times, gamma_, beta_, W1, b1, b2);

    dim3 pg((NZOUT + TB - 1) / TB, BATCH / 16);
    pred_kernel<<<pg, TB>>>(bpred, out);
}